// round 8
// baseline (speedup 1.0000x reference)
#include <cuda_runtime.h>
#include <cstdint>

#define L_SEQ   1024
#define BATCH   256
#define LB      (L_SEQ*BATCH)
#define KV      10648
#define NFRAG   32
#define KLEN    96
#define ROWS3L  (3*L_SEQ)

typedef unsigned long long ull;

// ---------------- device scratch ----------------
__device__ float4 g_Tk4[KV*16];            // kmer-fused table (10648 x 64)
__device__ float4 g_Ts4[20*16];            // seq-fused table (+b0)
__device__ float  g_ct[(size_t)ROWS3L*BATCH*3];  // c_tilde / frag (in place)
__device__ __align__(16) float g_R[NFRAG*BATCH*12];
__device__ int    g_seq[LB];
__device__ int    g_kmer[LB];
__device__ int    g_flag[2];

// ---------------- f32x2 helpers ----------------
__device__ __forceinline__ ull pk2(float x, float y){
    ull r; asm("mov.b64 %0,{%1,%2};" : "=l"(r) : "f"(x), "f"(y)); return r;
}
__device__ __forceinline__ float2 up2(ull a){
    float x,y; asm("mov.b64 {%0,%1},%2;" : "=f"(x), "=f"(y) : "l"(a));
    return make_float2(x,y);
}
__device__ __forceinline__ ull fma2(ull a, ull b, ull c){
    ull d; asm("fma.rn.f32x2 %0,%1,%2,%3;" : "=l"(d) : "l"(a), "l"(b), "l"(c));
    return d;
}
__device__ __forceinline__ ull relu2(ull a){
    float2 f = up2(a);
    return pk2(fmaxf(f.x, 0.f), fmaxf(f.y, 0.f));
}
__device__ __forceinline__ ull shflx1(ull v){
    unsigned lo = (unsigned)v, hi = (unsigned)(v >> 32);
    lo = __shfl_xor_sync(0xffffffffu, lo, 1);
    hi = __shfl_xor_sync(0xffffffffu, hi, 1);
    return ((ull)hi << 32) | (ull)lo;
}

// ---------------- dtype detect (int64 vs int32) ----------------
__global__ void k_detect(const int* __restrict__ s, const int* __restrict__ k){
    __shared__ int a0, a1;
    if (threadIdx.x == 0){ a0 = 0; a1 = 0; }
    __syncthreads();
    int a = 0, b = 0;
    for (int i = threadIdx.x; i < 4096; i += 256){ a |= s[2*i+1]; b |= k[2*i+1]; }
    if (a) atomicOr(&a0, 1);
    if (b) atomicOr(&a1, 1);
    __syncthreads();
    if (threadIdx.x == 0){ g_flag[0] = a0 ? 0 : 1; g_flag[1] = a1 ? 0 : 1; }
}
__global__ void k_conv(const int* __restrict__ s, const int* __restrict__ k){
    int f0 = g_flag[0], f1 = g_flag[1];
    for (int i = blockIdx.x*blockDim.x + threadIdx.x; i < LB; i += gridDim.x*blockDim.x){
        g_seq[i]  = f0 ? s[2*i] : s[i];
        g_kmer[i] = f1 ? k[2*i] : k[i];
    }
}

// ---------------- Tk table (+Ts fused in last block) ------------------
// 64 rows/block, 256 thr: lr=tid>>2 local row, q=tid&3 owns 16 cols.
// W0[16:272] staged 80KB smem, layout k*40 + q*10 + kk (bank-disjoint).
__global__ __launch_bounds__(256) void k_tk(const float* __restrict__ ke,
                                            const float* __restrict__ W0,
                                            const float* __restrict__ se,
                                            const float* __restrict__ b0){
    extern __shared__ ull w0k[];           // 256*40 ull = 80KB
    float* w0f = (float*)w0k;
    int tid = threadIdx.x;
    for (int i = tid; i < 16384; i += 256){
        int k = i >> 6, c = i & 63;
        int q = c >> 4, kk = (c & 15) >> 1, comp = c & 1;
        w0f[(k*40 + q*10 + kk)*2 + comp] = W0[1024 + i];
    }
    __syncthreads();
    int lr = tid >> 2, q = tid & 3;
    int r = blockIdx.x*64 + lr;
    bool valid = r < KV;
    const float4* kr = (const float4*)(ke + (valid ? (size_t)r*256 : 0));
    ull acc[8];
    #pragma unroll
    for (int i = 0; i < 8; i++) acc[i] = 0ull;
    #pragma unroll 4
    for (int k4 = 0; k4 < 64; k4++){
        float4 kv = __ldg(kr + k4);
        float sv[4] = {kv.x, kv.y, kv.z, kv.w};
        #pragma unroll
        for (int e = 0; e < 4; e++){
            ull hj = pk2(sv[e], sv[e]);
            const ull* wr = w0k + (k4*4 + e)*40 + q*10;
            #pragma unroll
            for (int k2 = 0; k2 < 4; k2++){
                ulonglong2 ww = *(const ulonglong2*)(wr + 2*k2);
                acc[2*k2]   = fma2(hj, ww.x, acc[2*k2]);
                acc[2*k2+1] = fma2(hj, ww.y, acc[2*k2+1]);
            }
        }
    }
    if (valid){
        float2* dst = (float2*)((float*)g_Tk4 + (size_t)r*64 + q*16);
        #pragma unroll
        for (int i = 0; i < 8; i++) dst[i] = up2(acc[i]);
    }
    // fused Ts table (tiny) in the last (partial) block
    if (blockIdx.x == 166 && tid < 64){
        int c = tid;
        float* Ts = (float*)g_Ts4;
        for (int s = 0; s < 20; s++){
            float a = b0[c];
            #pragma unroll
            for (int j = 0; j < 16; j++) a += se[s*16+j] * W0[j*64+c];
            Ts[s*64+c] = a;
        }
    }
}

// ---------------- main fused MLP (col-pair f32x2, register h) ----------
#define SWR 36
__global__ __launch_bounds__(128,3) void k_mlp(const float* __restrict__ pssm,
        const float* __restrict__ W0, const float* __restrict__ We,
        const float* __restrict__ be, const float* __restrict__ W1,
        const float* __restrict__ b1){
    __shared__ ull we2[64*SWR];    // [j][half*18 + kk]
    __shared__ ull w0p[21*SWR];
    __shared__ ull w1p[324];       // [halfc*162 + kk*10 + o]
    __shared__ ull bep[36];
    __shared__ float b1s[9];
    int tid = threadIdx.x, blk = blockIdx.x;

    for (int i = tid; i < 4096; i += 128){
        int j = i >> 6, c = i & 63;
        int half = c >> 5, kk = (c & 31) >> 1, comp = c & 1;
        ((float*)we2)[(j*SWR + half*18 + kk)*2 + comp] = We[i];
    }
    for (int i = tid; i < 1344; i += 128){
        int j = i >> 6, c = i & 63;
        int half = c >> 5, kk = (c & 31) >> 1, comp = c & 1;
        ((float*)w0p)[(j*SWR + half*18 + kk)*2 + comp] = W0[(272+j)*64 + c];
    }
    for (int i = tid; i < 576; i += 128){
        int j = i/9, o = i - j*9;
        int gk = j >> 1, comp = j & 1;
        ((float*)w1p)[((gk>>4)*162 + (gk&15)*10 + o)*2 + comp] = W1[i];
    }
    if (tid < 32){
        int half = tid >> 4, kk = tid & 15;
        bep[half*18 + kk] = pk2(be[half*32 + 2*kk], be[half*32 + 2*kk + 1]);
    }
    if (tid >= 32 && tid < 41) b1s[tid-32] = b1[tid-32];
    __syncthreads();

    int lane = tid & 31, w = tid >> 5;
    int pI = lane >> 1, halfc = lane & 1;
    int myoff = halfc*18;

    for (int ch = 0; ch < 2; ch++){
        int base = blk*256 + ch*128 + w*32;
        int tA = base + 2*pI, tB = tA + 1;
        int sA = g_seq[tA], sB = g_seq[tB];
        int kA = g_kmer[tA], kB = g_kmer[tB];

        ull accA[16], accB[16], hA[16], hB[16];
        #pragma unroll
        for (int q = 0; q < 8; q++){
            float4 ka = g_Tk4[kA*16 + (halfc<<3) + q];
            float4 ea = g_Ts4[sA*16 + (halfc<<3) + q];
            accA[2*q]   = pk2(ka.x+ea.x, ka.y+ea.y);
            accA[2*q+1] = pk2(ka.z+ea.z, ka.w+ea.w);
            float4 kb = g_Tk4[kB*16 + (halfc<<3) + q];
            float4 eb = g_Ts4[sB*16 + (halfc<<3) + q];
            accB[2*q]   = pk2(kb.x+eb.x, kb.y+eb.y);
            accB[2*q+1] = pk2(kb.z+eb.z, kb.w+eb.w);
        }
        const float* PA = pssm + (size_t)tA*21;
        const float* PB = pssm + (size_t)tB*21;
        #pragma unroll 3
        for (int j = 0; j < 21; j++){
            float pa = __ldg(PA + j), pb = __ldg(PB + j);
            ull hjA = pk2(pa, pa), hjB = pk2(pb, pb);
            const ull* wr = w0p + j*SWR + myoff;
            #pragma unroll
            for (int k2 = 0; k2 < 8; k2++){
                ulonglong2 ww = *(const ulonglong2*)(wr + 2*k2);
                accA[2*k2]   = fma2(hjA, ww.x, accA[2*k2]);
                accA[2*k2+1] = fma2(hjA, ww.y, accA[2*k2+1]);
                accB[2*k2]   = fma2(hjB, ww.x, accB[2*k2]);
                accB[2*k2+1] = fma2(hjB, ww.y, accB[2*k2+1]);
            }
        }
        #pragma unroll
        for (int kk = 0; kk < 16; kk++){ hA[kk] = accA[kk]; hB[kk] = accB[kk]; }

        // two relu(h @ We + be) layers; butterfly h exchange
        #pragma unroll 1
        for (int LL = 0; LL < 2; LL++){
            #pragma unroll
            for (int kk = 0; kk < 16; kk++){
                ull bv = bep[myoff + kk];
                accA[kk] = bv; accB[kk] = bv;
            }
            #pragma unroll
            for (int kk = 0; kk < 16; kk++){
                ull pA = shflx1(hA[kk]);
                ull pB = shflx1(hB[kk]);
                ull vA0 = halfc ? pA : hA[kk];   // h from pair-lane halfc==0
                ull vA1 = halfc ? hA[kk] : pA;   // h from pair-lane halfc==1
                ull vB0 = halfc ? pB : hB[kk];
                ull vB1 = halfc ? hB[kk] : pB;
                #pragma unroll
                for (int ow = 0; ow < 2; ow++){
                    ull vA = ow ? vA1 : vA0;
                    ull vB = ow ? vB1 : vB0;
                    #pragma unroll
                    for (int comp = 0; comp < 2; comp++){
                        int j = ow*32 + kk*2 + comp;
                        float2 fa = up2(vA); float sa = comp ? fa.y : fa.x;
                        float2 fb = up2(vB); float sb = comp ? fb.y : fb.x;
                        ull hjA = pk2(sa, sa), hjB = pk2(sb, sb);
                        const ull* wr = we2 + j*SWR + myoff;
                        #pragma unroll
                        for (int k2 = 0; k2 < 8; k2++){
                            ulonglong2 ww = *(const ulonglong2*)(wr + 2*k2);
                            accA[2*k2]   = fma2(hjA, ww.x, accA[2*k2]);
                            accA[2*k2+1] = fma2(hjA, ww.y, accA[2*k2+1]);
                            accB[2*k2]   = fma2(hjB, ww.x, accB[2*k2]);
                            accB[2*k2+1] = fma2(hjB, ww.y, accB[2*k2+1]);
                        }
                    }
                }
            }
            #pragma unroll
            for (int kk = 0; kk < 16; kk++){
                hA[kk] = relu2(accA[kk]);
                hB[kk] = relu2(accB[kk]);
            }
        }

        // final 64->9
        ull opA[9], opB[9];
        #pragma unroll
        for (int o = 0; o < 9; o++){ opA[o] = 0ull; opB[o] = 0ull; }
        #pragma unroll
        for (int kk = 0; kk < 16; kk++){
            const ull* wr = w1p + halfc*162 + kk*10;
            ull ha = hA[kk], hb = hB[kk];
            #pragma unroll
            for (int o = 0; o < 9; o++){
                ull ww = wr[o];
                opA[o] = fma2(ha, ww, opA[o]);
                opB[o] = fma2(hb, ww, opB[o]);
            }
        }
        int t = halfc ? tB : tA;
        int l = t >> 8, bb = t & 255;
        #pragma unroll
        for (int o = 0; o < 9; o++){
            float2 fa = up2(opA[o]); float va = fa.x + fa.y;
            va += __shfl_xor_sync(0xffffffffu, va, 1);
            float2 fb = up2(opB[o]); float vb = fb.x + fb.y;
            vb += __shfl_xor_sync(0xffffffffu, vb, 1);
            float v = (halfc ? vb : va) + b1s[o];
            int r = o/3, j3 = o - r*3;
            g_ct[((size_t)(3*l + r)*256 + bb)*3 + j3] = v;
        }
    }
}

// ---------------- fragment NeRF scan (ring-4 prefetch) ----------------
__global__ __launch_bounds__(128) void k_frag(){
    int tid = blockIdx.x*128 + threadIdx.x;   // 0..8191
    int b = tid & 255, f = tid >> 8;
    float pax = -0.70710678118654752f, pay = 1.22474487139158905f, paz = 0.f;
    float pbx = -1.41421356237309505f, pby = 0.f, pbz = 0.f;
    float pcx = 0.f, pcy = 0.f, pcz = 0.f;
    float nx[4], ny[4], nz[4];
    #pragma unroll
    for (int q = 0; q < 4; q++){
        size_t id = ((size_t)(f*KLEN + q)*256 + b)*3;
        nx[q] = g_ct[id]; ny[q] = g_ct[id+1]; nz[q] = g_ct[id+2];
    }
    #pragma unroll 1
    for (int t = 0; t < KLEN; t++){
        int s = t & 3;
        float tx = nx[s], ty = ny[s], tz = nz[s];
        if (t + 4 < KLEN){
            size_t id = ((size_t)(f*KLEN + t + 4)*256 + b)*3;
            nx[s] = g_ct[id]; ny[s] = g_ct[id+1]; nz[s] = g_ct[id+2];
        }
        float ux = pcx-pbx, uy = pcy-pby, uz = pcz-pbz;
        float sc = rsqrtf(fmaxf(ux*ux+uy*uy+uz*uz, 1e-24f));
        ux *= sc; uy *= sc; uz *= sc;
        float vx = pbx-pax, vy = pby-pay, vz = pbz-paz;
        float wx = vy*uz - vz*uy, wy = vz*ux - vx*uz, wz = vx*uy - vy*ux;
        float s2 = rsqrtf(fmaxf(wx*wx+wy*wy+wz*wz, 1e-24f));
        wx *= s2; wy *= s2; wz *= s2;
        float mx = wy*uz - wz*uy, my = wz*ux - wx*uz, mz = wx*uy - wy*ux;
        float dx = pcx + ux*tx + mx*ty + wx*tz;
        float dy = pcy + uy*tx + my*ty + wy*tz;
        float dz = pcz + uz*tx + mz*ty + wz*tz;
        size_t od = ((size_t)(f*KLEN + t)*256 + b)*3;
        g_ct[od] = dx; g_ct[od+1] = dy; g_ct[od+2] = dz;
        pax = pbx; pay = pby; paz = pbz;
        pbx = pcx; pby = pcy; pbz = pcz;
        pcx = dx;  pcy = dy;  pcz = dz;
    }
}

// ---------------- assembly carry chain ----------------
__global__ void k_carry(){
    int b = threadIdx.x;
    float pax = -0.70710678118654752f, pay = 1.22474487139158905f, paz = 0.f;
    float pbx = -1.41421356237309505f, pby = 0.f, pbz = 0.f;
    float pcx = 0.f, pcy = 0.f, pcz = 0.f;
    for (int f = 0; f < NFRAG; f++){
        float ux = pcx-pbx, uy = pcy-pby, uz = pcz-pbz;
        float s = rsqrtf(fmaxf(ux*ux+uy*uy+uz*uz, 1e-24f));
        ux *= s; uy *= s; uz *= s;
        float vx = pbx-pax, vy = pby-pay, vz = pbz-paz;
        float wx = vy*uz - vz*uy, wy = vz*ux - vx*uz, wz = vx*uy - vy*ux;
        float s2 = rsqrtf(fmaxf(wx*wx+wy*wy+wz*wz, 1e-24f));
        wx *= s2; wy *= s2; wz *= s2;
        float mx = wy*uz - wz*uy, my = wz*ux - wx*uz, mz = wx*uy - wy*ux;
        float* R = g_R + ((size_t)f*256 + b)*12;
        R[0]=ux; R[1]=uy; R[2]=uz;
        R[3]=mx; R[4]=my; R[5]=mz;
        R[6]=wx; R[7]=wy; R[8]=wz;
        R[9]=pcx; R[10]=pcy; R[11]=pcz;
        float yx[3], yy[3], yz[3];
        #pragma unroll
        for (int i = 0; i < 3; i++){
            size_t id = ((size_t)(f*KLEN + 93 + i)*256 + b)*3;
            float px = g_ct[id], py = g_ct[id+1], pz = g_ct[id+2];
            yx[i] = pcx + ux*px + mx*py + wx*pz;
            yy[i] = pcy + uy*px + my*py + wy*pz;
            yz[i] = pcz + uz*px + mz*py + wz*pz;
        }
        pax = yx[0]; pay = yy[0]; paz = yz[0];
        pbx = yx[1]; pby = yy[1]; pbz = yz[1];
        pcx = yx[2]; pcy = yy[2]; pcz = yz[2];
    }
}

// ---------------- apply rigid transforms (8 t per block) ----------------
__global__ __launch_bounds__(256) void k_apply(float* __restrict__ out){
    int f = blockIdx.y;
    int t0 = blockIdx.x * 8;
    int b = threadIdx.x;
    const float4* R4 = (const float4*)g_R;
    float4 q0 = R4[(f*256 + b)*3 + 0];
    float4 q1 = R4[(f*256 + b)*3 + 1];
    float4 q2 = R4[(f*256 + b)*3 + 2];
    #pragma unroll
    for (int dt = 0; dt < 8; dt++){
        int t = t0 + dt;
        size_t id = ((size_t)(f*KLEN + t)*256 + b)*3;
        float px = g_ct[id], py = g_ct[id+1], pz = g_ct[id+2];
        out[id]   = q2.y + q0.x*px + q0.w*py + q1.z*pz;
        out[id+1] = q2.z + q0.y*px + q1.x*py + q1.w*pz;
        out[id+2] = q2.w + q0.z*px + q1.y*py + q2.x*pz;
    }
}

extern "C" void kernel_launch(void* const* d_in, const int* in_sizes, int n_in,
                              void* d_out, int out_size){
    const int*   seq  = (const int*)d_in[0];
    const int*   kmer = (const int*)d_in[1];
    const float* pssm = (const float*)d_in[2];
    const float* se   = (const float*)d_in[4];
    const float* ke   = (const float*)d_in[5];
    const float* W0   = (const float*)d_in[6];
    const float* b0   = (const float*)d_in[7];
    const float* We   = (const float*)d_in[8];
    const float* be   = (const float*)d_in[9];
    const float* W1   = (const float*)d_in[10];
    const float* b1   = (const float*)d_in[11];

    cudaFuncSetAttribute(k_tk, cudaFuncAttributeMaxDynamicSharedMemorySize, 81920);

    k_detect<<<1,256>>>(seq, kmer);
    k_conv<<<264,256>>>(seq, kmer);
    k_tk<<<167,256,81920>>>(ke, W0, se, b0);
    k_mlp<<<LB/256,128>>>(pssm, W0, We, be, W1, b1);
    k_frag<<<64,128>>>();
    k_carry<<<1,256>>>();
    dim3 ga(12, 32);
    k_apply<<<ga,256>>>((float*)d_out);
}

// round 9
// speedup vs baseline: 1.0305x; 1.0305x over previous
#include <cuda_runtime.h>
#include <cstdint>

#define L_SEQ   1024
#define BATCH   256
#define LB      (L_SEQ*BATCH)
#define KV      10648
#define NFRAG   32
#define KLEN    96
#define ROWS3L  (3*L_SEQ)

typedef unsigned long long ull;

// ---------------- device scratch ----------------
__device__ float4 g_Tk4[KV*16];            // kmer-fused table (10648 x 64)
__device__ float4 g_Ts4[20*16];            // seq-fused table (+b0)
__device__ float  g_ct[(size_t)ROWS3L*BATCH*3];  // c_tilde / frag (in place)
__device__ __align__(16) float g_R[NFRAG*BATCH*12];
__device__ int    g_seq[LB];
__device__ int    g_kmer[LB];
__device__ int    g_flag[2];

// ---------------- f32x2 helpers ----------------
__device__ __forceinline__ ull pk2(float x, float y){
    ull r; asm("mov.b64 %0,{%1,%2};" : "=l"(r) : "f"(x), "f"(y)); return r;
}
__device__ __forceinline__ float2 up2(ull a){
    float x,y; asm("mov.b64 {%0,%1},%2;" : "=f"(x), "=f"(y) : "l"(a));
    return make_float2(x,y);
}
__device__ __forceinline__ ull fma2(ull a, ull b, ull c){
    ull d; asm("fma.rn.f32x2 %0,%1,%2,%3;" : "=l"(d) : "l"(a), "l"(b), "l"(c));
    return d;
}
__device__ __forceinline__ ull relu2(ull a){
    float2 f = up2(a);
    return pk2(fmaxf(f.x, 0.f), fmaxf(f.y, 0.f));
}
__device__ __forceinline__ ull shflx1(ull v){
    unsigned lo = (unsigned)v, hi = (unsigned)(v >> 32);
    lo = __shfl_xor_sync(0xffffffffu, lo, 1);
    hi = __shfl_xor_sync(0xffffffffu, hi, 1);
    return ((ull)hi << 32) | (ull)lo;
}

// ---------------- dtype detect (int64 vs int32) ----------------
__global__ void k_detect(const int* __restrict__ s, const int* __restrict__ k){
    __shared__ int a0, a1;
    if (threadIdx.x == 0){ a0 = 0; a1 = 0; }
    __syncthreads();
    int a = 0, b = 0;
    for (int i = threadIdx.x; i < 4096; i += 256){ a |= s[2*i+1]; b |= k[2*i+1]; }
    if (a) atomicOr(&a0, 1);
    if (b) atomicOr(&a1, 1);
    __syncthreads();
    if (threadIdx.x == 0){ g_flag[0] = a0 ? 0 : 1; g_flag[1] = a1 ? 0 : 1; }
}
__global__ void k_conv(const int* __restrict__ s, const int* __restrict__ k){
    int f0 = g_flag[0], f1 = g_flag[1];
    for (int i = blockIdx.x*blockDim.x + threadIdx.x; i < LB; i += gridDim.x*blockDim.x){
        g_seq[i]  = f0 ? s[2*i] : s[i];
        g_kmer[i] = f1 ? k[2*i] : k[i];
    }
}

// ---------------- Tk table (+Ts fused in last block) ------------------
__global__ __launch_bounds__(256) void k_tk(const float* __restrict__ ke,
                                            const float* __restrict__ W0,
                                            const float* __restrict__ se,
                                            const float* __restrict__ b0){
    extern __shared__ ull w0k[];           // 256*40 ull = 80KB
    float* w0f = (float*)w0k;
    int tid = threadIdx.x;
    for (int i = tid; i < 16384; i += 256){
        int k = i >> 6, c = i & 63;
        int q = c >> 4, kk = (c & 15) >> 1, comp = c & 1;
        w0f[(k*40 + q*10 + kk)*2 + comp] = W0[1024 + i];
    }
    __syncthreads();
    int lr = tid >> 2, q = tid & 3;
    int r = blockIdx.x*64 + lr;
    bool valid = r < KV;
    const float4* kr = (const float4*)(ke + (valid ? (size_t)r*256 : 0));
    ull acc[8];
    #pragma unroll
    for (int i = 0; i < 8; i++) acc[i] = 0ull;
    #pragma unroll 4
    for (int k4 = 0; k4 < 64; k4++){
        float4 kv = __ldg(kr + k4);
        float sv[4] = {kv.x, kv.y, kv.z, kv.w};
        #pragma unroll
        for (int e = 0; e < 4; e++){
            ull hj = pk2(sv[e], sv[e]);
            const ull* wr = w0k + (k4*4 + e)*40 + q*10;
            #pragma unroll
            for (int k2 = 0; k2 < 4; k2++){
                ulonglong2 ww = *(const ulonglong2*)(wr + 2*k2);
                acc[2*k2]   = fma2(hj, ww.x, acc[2*k2]);
                acc[2*k2+1] = fma2(hj, ww.y, acc[2*k2+1]);
            }
        }
    }
    if (valid){
        float2* dst = (float2*)((float*)g_Tk4 + (size_t)r*64 + q*16);
        #pragma unroll
        for (int i = 0; i < 8; i++) dst[i] = up2(acc[i]);
    }
    if (blockIdx.x == 166 && tid < 64){
        int c = tid;
        float* Ts = (float*)g_Ts4;
        for (int s = 0; s < 20; s++){
            float a = b0[c];
            #pragma unroll
            for (int j = 0; j < 16; j++) a += se[s*16+j] * W0[j*64+c];
            Ts[s*64+c] = a;
        }
    }
}

// ---------------- main fused MLP (col-pair f32x2, register h) ----------
#define SWR 36
__global__ __launch_bounds__(128,3) void k_mlp(const float* __restrict__ pssm,
        const float* __restrict__ W0, const float* __restrict__ We,
        const float* __restrict__ be, const float* __restrict__ W1,
        const float* __restrict__ b1){
    __shared__ ull we2[64*SWR];    // [j][half*18 + kk]
    __shared__ ull w0p[21*SWR];
    __shared__ ull w1p[324];       // [halfc*162 + kk*10 + o]
    __shared__ ull bep[36];
    __shared__ float b1s[9];
    int tid = threadIdx.x, blk = blockIdx.x;

    for (int i = tid; i < 4096; i += 128){
        int j = i >> 6, c = i & 63;
        int half = c >> 5, kk = (c & 31) >> 1, comp = c & 1;
        ((float*)we2)[(j*SWR + half*18 + kk)*2 + comp] = We[i];
    }
    for (int i = tid; i < 1344; i += 128){
        int j = i >> 6, c = i & 63;
        int half = c >> 5, kk = (c & 31) >> 1, comp = c & 1;
        ((float*)w0p)[(j*SWR + half*18 + kk)*2 + comp] = W0[(272+j)*64 + c];
    }
    for (int i = tid; i < 576; i += 128){
        int j = i/9, o = i - j*9;
        int gk = j >> 1, comp = j & 1;
        ((float*)w1p)[((gk>>4)*162 + (gk&15)*10 + o)*2 + comp] = W1[i];
    }
    if (tid < 32){
        int half = tid >> 4, kk = tid & 15;
        bep[half*18 + kk] = pk2(be[half*32 + 2*kk], be[half*32 + 2*kk + 1]);
    }
    if (tid >= 32 && tid < 41) b1s[tid-32] = b1[tid-32];
    __syncthreads();

    int lane = tid & 31, w = tid >> 5;
    int pI = lane >> 1, halfc = lane & 1;
    int myoff = halfc*18;

    for (int ch = 0; ch < 2; ch++){
        int base = blk*256 + ch*128 + w*32;
        int tA = base + 2*pI, tB = tA + 1;
        int sA = g_seq[tA], sB = g_seq[tB];
        int kA = g_kmer[tA], kB = g_kmer[tB];

        ull accA[16], accB[16], hA[16], hB[16];
        #pragma unroll
        for (int q = 0; q < 8; q++){
            float4 ka = g_Tk4[kA*16 + (halfc<<3) + q];
            float4 ea = g_Ts4[sA*16 + (halfc<<3) + q];
            accA[2*q]   = pk2(ka.x+ea.x, ka.y+ea.y);
            accA[2*q+1] = pk2(ka.z+ea.z, ka.w+ea.w);
            float4 kb = g_Tk4[kB*16 + (halfc<<3) + q];
            float4 eb = g_Ts4[sB*16 + (halfc<<3) + q];
            accB[2*q]   = pk2(kb.x+eb.x, kb.y+eb.y);
            accB[2*q+1] = pk2(kb.z+eb.z, kb.w+eb.w);
        }
        const float* PA = pssm + (size_t)tA*21;
        const float* PB = pssm + (size_t)tB*21;
        #pragma unroll 3
        for (int j = 0; j < 21; j++){
            float pa = __ldg(PA + j), pb = __ldg(PB + j);
            ull hjA = pk2(pa, pa), hjB = pk2(pb, pb);
            const ull* wr = w0p + j*SWR + myoff;
            #pragma unroll
            for (int k2 = 0; k2 < 8; k2++){
                ulonglong2 ww = *(const ulonglong2*)(wr + 2*k2);
                accA[2*k2]   = fma2(hjA, ww.x, accA[2*k2]);
                accA[2*k2+1] = fma2(hjA, ww.y, accA[2*k2+1]);
                accB[2*k2]   = fma2(hjB, ww.x, accB[2*k2]);
                accB[2*k2+1] = fma2(hjB, ww.y, accB[2*k2+1]);
            }
        }
        #pragma unroll
        for (int kk = 0; kk < 16; kk++){ hA[kk] = accA[kk]; hB[kk] = accB[kk]; }

        // two relu(h @ We + be) layers; butterfly h exchange
        #pragma unroll 1
        for (int LL = 0; LL < 2; LL++){
            #pragma unroll
            for (int kk = 0; kk < 16; kk++){
                ull bv = bep[myoff + kk];
                accA[kk] = bv; accB[kk] = bv;
            }
            #pragma unroll
            for (int kk = 0; kk < 16; kk++){
                ull pA = shflx1(hA[kk]);
                ull pB = shflx1(hB[kk]);
                ull vA0 = halfc ? pA : hA[kk];
                ull vA1 = halfc ? hA[kk] : pA;
                ull vB0 = halfc ? pB : hB[kk];
                ull vB1 = halfc ? hB[kk] : pB;
                #pragma unroll
                for (int ow = 0; ow < 2; ow++){
                    ull vA = ow ? vA1 : vA0;
                    ull vB = ow ? vB1 : vB0;
                    #pragma unroll
                    for (int comp = 0; comp < 2; comp++){
                        int j = ow*32 + kk*2 + comp;
                        float2 fa = up2(vA); float sa = comp ? fa.y : fa.x;
                        float2 fb = up2(vB); float sb = comp ? fb.y : fb.x;
                        ull hjA = pk2(sa, sa), hjB = pk2(sb, sb);
                        const ull* wr = we2 + j*SWR + myoff;
                        #pragma unroll
                        for (int k2 = 0; k2 < 8; k2++){
                            ulonglong2 ww = *(const ulonglong2*)(wr + 2*k2);
                            accA[2*k2]   = fma2(hjA, ww.x, accA[2*k2]);
                            accA[2*k2+1] = fma2(hjA, ww.y, accA[2*k2+1]);
                            accB[2*k2]   = fma2(hjB, ww.x, accB[2*k2]);
                            accB[2*k2+1] = fma2(hjB, ww.y, accB[2*k2+1]);
                        }
                    }
                }
            }
            #pragma unroll
            for (int kk = 0; kk < 16; kk++){
                hA[kk] = relu2(accA[kk]);
                hB[kk] = relu2(accB[kk]);
            }
        }

        // final 64->9
        ull opA[9], opB[9];
        #pragma unroll
        for (int o = 0; o < 9; o++){ opA[o] = 0ull; opB[o] = 0ull; }
        #pragma unroll
        for (int kk = 0; kk < 16; kk++){
            const ull* wr = w1p + halfc*162 + kk*10;
            ull ha = hA[kk], hb = hB[kk];
            #pragma unroll
            for (int o = 0; o < 9; o++){
                ull ww = wr[o];
                opA[o] = fma2(ha, ww, opA[o]);
                opB[o] = fma2(hb, ww, opB[o]);
            }
        }
        int t = halfc ? tB : tA;
        int l = t >> 8, bb = t & 255;
        #pragma unroll
        for (int o = 0; o < 9; o++){
            float2 fa = up2(opA[o]); float va = fa.x + fa.y;
            va += __shfl_xor_sync(0xffffffffu, va, 1);
            float2 fb = up2(opB[o]); float vb = fb.x + fb.y;
            vb += __shfl_xor_sync(0xffffffffu, vb, 1);
            float v = (halfc ? vb : va) + b1s[o];
            int r = o/3, j3 = o - r*3;
            g_ct[((size_t)(3*l + r)*256 + bb)*3 + j3] = v;
        }
    }
}

// ---------------- fragment NeRF scan (explicit 2-reg ring) ------------
__global__ __launch_bounds__(256) void k_frag(){
    int tid = blockIdx.x*256 + threadIdx.x;   // 0..8191
    int b = tid & 255, f = tid >> 8;
    float pax = -0.70710678118654752f, pay = 1.22474487139158905f, paz = 0.f;
    float pbx = -1.41421356237309505f, pby = 0.f, pbz = 0.f;
    float pcx = 0.f, pcy = 0.f, pcz = 0.f;
    float n0x, n0y, n0z, n1x, n1y, n1z;
    {
        size_t id = ((size_t)(f*KLEN)*256 + b)*3;
        n0x = g_ct[id]; n0y = g_ct[id+1]; n0z = g_ct[id+2];
        id += 256*3;
        n1x = g_ct[id]; n1y = g_ct[id+1]; n1z = g_ct[id+2];
    }
    #pragma unroll 1
    for (int t = 0; t < KLEN; t++){
        float tx = n0x, ty = n0y, tz = n0z;
        n0x = n1x; n0y = n1y; n0z = n1z;
        if (t + 2 < KLEN){
            size_t id = ((size_t)(f*KLEN + t + 2)*256 + b)*3;
            n1x = g_ct[id]; n1y = g_ct[id+1]; n1z = g_ct[id+2];
        }
        float ux = pcx-pbx, uy = pcy-pby, uz = pcz-pbz;
        float s = rsqrtf(fmaxf(ux*ux+uy*uy+uz*uz, 1e-24f));
        ux *= s; uy *= s; uz *= s;
        float vx = pbx-pax, vy = pby-pay, vz = pbz-paz;
        float wx = vy*uz - vz*uy, wy = vz*ux - vx*uz, wz = vx*uy - vy*ux;
        float s2 = rsqrtf(fmaxf(wx*wx+wy*wy+wz*wz, 1e-24f));
        wx *= s2; wy *= s2; wz *= s2;
        float mx = wy*uz - wz*uy, my = wz*ux - wx*uz, mz = wx*uy - wy*ux;
        float dx = pcx + ux*tx + mx*ty + wx*tz;
        float dy = pcy + uy*tx + my*ty + wy*tz;
        float dz = pcz + uz*tx + mz*ty + wz*tz;
        size_t od = ((size_t)(f*KLEN + t)*256 + b)*3;
        g_ct[od] = dx; g_ct[od+1] = dy; g_ct[od+2] = dz;
        pax = pbx; pay = pby; paz = pbz;
        pbx = pcx; pby = pcy; pbz = pcz;
        pcx = dx;  pcy = dy;  pcz = dz;
    }
}

// ---------------- assembly carry chain ----------------
__global__ void k_carry(){
    int b = threadIdx.x;
    float pax = -0.70710678118654752f, pay = 1.22474487139158905f, paz = 0.f;
    float pbx = -1.41421356237309505f, pby = 0.f, pbz = 0.f;
    float pcx = 0.f, pcy = 0.f, pcz = 0.f;
    for (int f = 0; f < NFRAG; f++){
        float ux = pcx-pbx, uy = pcy-pby, uz = pcz-pbz;
        float s = rsqrtf(fmaxf(ux*ux+uy*uy+uz*uz, 1e-24f));
        ux *= s; uy *= s; uz *= s;
        float vx = pbx-pax, vy = pby-pay, vz = pbz-paz;
        float wx = vy*uz - vz*uy, wy = vz*ux - vx*uz, wz = vx*uy - vy*ux;
        float s2 = rsqrtf(fmaxf(wx*wx+wy*wy+wz*wz, 1e-24f));
        wx *= s2; wy *= s2; wz *= s2;
        float mx = wy*uz - wz*uy, my = wz*ux - wx*uz, mz = wx*uy - wy*ux;
        float* R = g_R + ((size_t)f*256 + b)*12;
        R[0]=ux; R[1]=uy; R[2]=uz;
        R[3]=mx; R[4]=my; R[5]=mz;
        R[6]=wx; R[7]=wy; R[8]=wz;
        R[9]=pcx; R[10]=pcy; R[11]=pcz;
        float yx[3], yy[3], yz[3];
        #pragma unroll
        for (int i = 0; i < 3; i++){
            size_t id = ((size_t)(f*KLEN + 93 + i)*256 + b)*3;
            float px = g_ct[id], py = g_ct[id+1], pz = g_ct[id+2];
            yx[i] = pcx + ux*px + mx*py + wx*pz;
            yy[i] = pcy + uy*px + my*py + wy*pz;
            yz[i] = pcz + uz*px + mz*py + wz*pz;
        }
        pax = yx[0]; pay = yy[0]; paz = yz[0];
        pbx = yx[1]; pby = yy[1]; pbz = yz[1];
        pcx = yx[2]; pcy = yy[2]; pcz = yz[2];
    }
}

// ---------------- apply rigid transforms (8 t per block) ----------------
__global__ __launch_bounds__(256) void k_apply(float* __restrict__ out){
    int f = blockIdx.y;
    int t0 = blockIdx.x * 8;
    int b = threadIdx.x;
    const float4* R4 = (const float4*)g_R;
    float4 q0 = R4[(f*256 + b)*3 + 0];
    float4 q1 = R4[(f*256 + b)*3 + 1];
    float4 q2 = R4[(f*256 + b)*3 + 2];
    #pragma unroll
    for (int dt = 0; dt < 8; dt++){
        int t = t0 + dt;
        size_t id = ((size_t)(f*KLEN + t)*256 + b)*3;
        float px = g_ct[id], py = g_ct[id+1], pz = g_ct[id+2];
        out[id]   = q2.y + q0.x*px + q0.w*py + q1.z*pz;
        out[id+1] = q2.z + q0.y*px + q1.x*py + q1.w*pz;
        out[id+2] = q2.w + q0.z*px + q1.y*py + q2.x*pz;
    }
}

extern "C" void kernel_launch(void* const* d_in, const int* in_sizes, int n_in,
                              void* d_out, int out_size){
    const int*   seq  = (const int*)d_in[0];
    const int*   kmer = (const int*)d_in[1];
    const float* pssm = (const float*)d_in[2];
    const float* se   = (const float*)d_in[4];
    const float* ke   = (const float*)d_in[5];
    const float* W0   = (const float*)d_in[6];
    const float* b0   = (const float*)d_in[7];
    const float* We   = (const float*)d_in[8];
    const float* be   = (const float*)d_in[9];
    const float* W1   = (const float*)d_in[10];
    const float* b1   = (const float*)d_in[11];

    cudaFuncSetAttribute(k_tk, cudaFuncAttributeMaxDynamicSharedMemorySize, 81920);

    k_detect<<<1,256>>>(seq, kmer);
    k_conv<<<264,256>>>(seq, kmer);
    k_tk<<<167,256,81920>>>(ke, W0, se, b0);
    k_mlp<<<LB/256,128>>>(pssm, W0, We, be, W1, b1);
    k_frag<<<32,256>>>();
    k_carry<<<1,256>>>();
    dim3 ga(12, 32);
    k_apply<<<ga,256>>>((float*)d_out);
}